// round 13
// baseline (speedup 1.0000x reference)
#include <cuda_runtime.h>
#include <cuda_fp16.h>
#include <cstdint>
#include <math.h>

#define kVocab 50000
#define kEmbed 300
#define kEmbP  320
#define kUnits 512
#define kT 128
#define kB 512
#define kG 2048

// ---------------- global scratch ----------------
__device__ float g_zpre[(size_t)kB * kT * kG];
__device__ unsigned g_bar[8];
// U^T gate-interleaved fp16, resident-layout: [nt(16)][row n'(128) x 1024B swizzled rows]
//   elem idx = nt*65536 + rl*512 + ((q&56)|((q^rl)&7))*8 + ln   (q=k>>3, ln=k&7)
__device__ __align__(128) __half g_ur[16 * 128 * kUnits];
// h fp16 exchange staging, double buffered: [buf][mt(8)][row rb(64) x 1024B swizzled rows]
__device__ __align__(128) __half g_hx[2][8 * 64 * kUnits];
__device__ __align__(128) __half g_emb_hi[(size_t)kVocab * kEmbP];
__device__ __align__(128) __half g_emb_lo[(size_t)kVocab * kEmbP];
__device__ __align__(128) __half g_wt[kG * kEmbP];

// ---------------- helpers ----------------
__device__ __forceinline__ uint32_t smem_u32(const void* p) {
    uint32_t a;
    asm("{ .reg .u64 t; cvta.to.shared.u64 t, %1; cvt.u32.u64 %0, t; }" : "=r"(a) : "l"(p));
    return a;
}
#define CP_ASYNC16(dst, src) \
    asm volatile("cp.async.cg.shared.global [%0], [%1], 16;" :: "r"(dst), "l"(src) : "memory")
#define CP_COMMIT() asm volatile("cp.async.commit_group;" ::: "memory")
#define CP_WAIT0()  asm volatile("cp.async.wait_group 0;" ::: "memory")

#define MBAR_INIT(a, c) \
    asm volatile("mbarrier.init.shared.b64 [%0], %1;" :: "r"(a), "r"(c) : "memory")
#define MBAR_EXPECT_TX(a, bytes) \
    asm volatile("mbarrier.arrive.expect_tx.shared.b64 _, [%0], %1;" :: "r"(a), "r"(bytes) : "memory")
#define TMA_BULK(dst, src, sz, mbar) \
    asm volatile("cp.async.bulk.shared::cta.global.mbarrier::complete_tx::bytes [%0], [%1], %2, [%3];" \
        :: "r"(dst), "l"(src), "r"(sz), "r"(mbar) : "memory")
#define MBAR_WAIT(a, par) do { \
    uint32_t _m = (a), _p = (par), _d; \
    asm volatile("{ .reg .pred p; mbarrier.try_wait.parity.acquire.cta.shared::cta.b64 p, [%1], %2; selp.b32 %0,1,0,p; }" \
        : "=r"(_d) : "r"(_m), "r"(_p) : "memory"); \
    if (!_d) { \
        asm volatile("{ .reg .pred P1; WL%=: mbarrier.try_wait.parity.acquire.cta.shared::cta.b64 P1, [%0], %1, 0x989680; @P1 bra.uni WD%=; bra.uni WL%=; WD%=: }" \
            :: "r"(_m), "r"(_p) : "memory"); \
    } } while (0)

#define LDMATRIX_X4(r0, r1, r2, r3, addr) \
    asm volatile("ldmatrix.sync.aligned.m8n8.x4.shared.b16 {%0,%1,%2,%3}, [%4];" \
        : "=r"(r0), "=r"(r1), "=r"(r2), "=r"(r3) : "r"(addr))

#define MMA_F16(c0, c1, c2, c3, a0, a1, a2, a3, b0, b1) \
    asm volatile("mma.sync.aligned.m16n8k16.row.col.f32.f16.f16.f32 " \
        "{%0,%1,%2,%3}, {%4,%5,%6,%7}, {%8,%9}, {%0,%1,%2,%3};" \
        : "+f"(c0), "+f"(c1), "+f"(c2), "+f"(c3) \
        : "r"(a0), "r"(a1), "r"(a2), "r"(a3), "r"(b0), "r"(b1))

__device__ __forceinline__ float fast_ex2(float x) { float y; asm("ex2.approx.ftz.f32 %0, %1;" : "=f"(y) : "f"(x)); return y; }
__device__ __forceinline__ float fast_sig(float x) { return __fdividef(1.f, 1.f + fast_ex2(-1.4426950408889634f * x)); }
__device__ __forceinline__ float fast_tanh(float x) {
    float ax = fabsf(x);
    float e = fast_ex2(-2.8853900817779268f * ax);
    float t = __fdividef(1.f - e, 1.f + e);
    return copysignf(t, x);
}
__device__ __forceinline__ void split_f16(float v, __half& hi, __half& lo) {
    hi = __float2half_rn(v);
    lo = __float2half_rn(v - __half2float(hi));
}

// ---------------- prep ----------------
__global__ __launch_bounds__(128) void prep_kernel(const float* __restrict__ U,
                                                   const float* __restrict__ h0,
                                                   const float* __restrict__ W,
                                                   const float* __restrict__ emb) {
    int blk = blockIdx.x;
    if (blk == 0 && threadIdx.x < 8) g_bar[threadIdx.x] = 0;
    if (blk < kG) {                       // U^T gate-interleaved n'=u*4+g -> resident layout
        int np = blk;
        int n = (np & 3) * kUnits + (np >> 2);
        int nt = np >> 7, rl = np & 127;
        for (int k = threadIdx.x; k < kUnits; k += 128) {
            int q = k >> 3, ln = k & 7;
            size_t idx = (size_t)nt * 65536 + rl * 512 + ((q & 56) | ((q ^ rl) & 7)) * 8 + ln;
            g_ur[idx] = __float2half_rn(__ldg(U + (size_t)k * kG + n));
        }
    } else if (blk < kG + 8) {            // h0 -> fp16 swizzled rows, exchange buffer 0
        int mt = blk - kG;
        int r0 = mt * 64;
        for (int i = threadIdx.x; i < 64 * kUnits; i += 128) {
            int rb = i >> 9, k = i & 511;
            int q = k >> 3, ln = k & 7;
            size_t idx = (size_t)mt * 32768 + rb * 512 + ((q & 56) | ((q ^ rb) & 7)) * 8 + ln;
            g_hx[0][idx] = __float2half_rn(__ldg(h0 + (size_t)(r0 + rb) * kUnits + k));
        }
    } else if (blk < kG + 8 + kG) {       // W^T row n, padded K, fp16
        int n = blk - kG - 8;
        for (int k = threadIdx.x; k < kEmbP; k += 128) {
            float v = (k < kEmbed) ? __ldg(W + (size_t)k * kG + n) : 0.f;
            g_wt[n * kEmbP + k] = __float2half_rn(v);
        }
    } else {                              // emb rows, padded, fp16 hi/lo
        int r0 = (blk - kG - 8 - kG) * 8;
        for (int rr = 0; rr < 8; rr++) {
            int row = r0 + rr;
            if (row >= kVocab) break;
            for (int k = threadIdx.x; k < kEmbP; k += 128) {
                float v = (k < kEmbed) ? __ldg(emb + (size_t)row * kEmbed + k) : 0.f;
                __half hi, lo;
                split_f16(v, hi, lo);
                g_emb_hi[(size_t)row * kEmbP + k] = hi;
                g_emb_lo[(size_t)row * kEmbP + k] = lo;
            }
        }
    }
}

// ---------------- precompute Zpre via mma.sync (R10/R11, proven) ----------------
#define PC_STG 49152
#define PC_DYN 98304

extern "C" __global__ void __launch_bounds__(256, 1) precompute_mma_kernel(
    const int* __restrict__ seq, const float* __restrict__ bias)
{
    extern __shared__ __align__(1024) char smp[];
    const uint32_t smb = smem_u32(smp);
    __shared__ int toks[128];

    const int tid = threadIdx.x;
    const int wid = tid >> 5, lane = tid & 31;
    const int nt = blockIdx.x, b = blockIdx.y;
    const int n0 = nt * 128;

    if (tid < 128) toks[tid] = seq[(size_t)b * kT + tid];
    __syncthreads();

    const int wm = (wid & 1) * 64;
    const int wn = (wid >> 1) * 32;

    float acc[4][4][4];
#pragma unroll
    for (int i = 0; i < 4; i++)
#pragma unroll
        for (int j = 0; j < 4; j++)
#pragma unroll
            for (int q = 0; q < 4; q++) acc[i][j][q] = 0.f;

    auto issue_chunk = [&](int kc, int stg) {
#pragma unroll
        for (int i = 0; i < 12; i++) {
            int idx = i * 256 + tid;
            uint32_t dst;
            const __half* src;
            if (idx < 2048) {
                int mat = idx >> 10, r = (idx >> 3) & 127, q = idx & 7;
                src = (mat ? g_emb_lo : g_emb_hi) + (size_t)toks[r] * kEmbP + kc * 64 + q * 8;
                uint32_t off = (uint32_t)(r * 128 + ((q ^ (r & 7)) * 16));
                dst = smb + stg * PC_STG + mat * 16384 + off;
            } else {
                int idxB = idx - 2048;
                int r = (idxB >> 3) & 127, q = idxB & 7;
                src = g_wt + (size_t)(n0 + r) * kEmbP + kc * 64 + q * 8;
                uint32_t off = (uint32_t)(r * 128 + ((q ^ (r & 7)) * 16));
                dst = smb + stg * PC_STG + 32768 + off;
            }
            CP_ASYNC16(dst, src);
        }
        CP_COMMIT();
    };

    issue_chunk(0, 0);

    const int la7 = lane & 7;
    const int arow_off = (lane >> 3) & 1;
    const int akseg   = (lane >> 4) & 1;
    const int brow_off = (lane >> 4) & 1;
    const int bkseg   = (lane >> 3) & 1;

    for (int kc = 0; kc < 5; kc++) {
        CP_WAIT0();
        __syncthreads();
        if (kc < 4) issue_chunk(kc + 1, (kc + 1) & 1);

        const uint32_t base = smb + (kc & 1) * PC_STG;
#pragma unroll
        for (int ks = 0; ks < 4; ks++) {
            uint32_t ahi[4][4], alo[4][4], bb[2][4];
#pragma unroll
            for (int mf = 0; mf < 4; mf++) {
                int row = wm + mf * 16 + la7 + arow_off * 8;
                uint32_t off = (uint32_t)(row * 128 + ks * 32 + akseg * 16);
                off ^= (uint32_t)((row & 7) * 16);
                LDMATRIX_X4(ahi[mf][0], ahi[mf][1], ahi[mf][2], ahi[mf][3], base + off);
                LDMATRIX_X4(alo[mf][0], alo[mf][1], alo[mf][2], alo[mf][3], base + 16384 + off);
            }
#pragma unroll
            for (int p = 0; p < 2; p++) {
                int row = wn + p * 16 + la7 + brow_off * 8;
                uint32_t off = (uint32_t)(row * 128 + ks * 32 + bkseg * 16);
                off ^= (uint32_t)((row & 7) * 16);
                LDMATRIX_X4(bb[p][0], bb[p][1], bb[p][2], bb[p][3], base + 32768 + off);
            }
#pragma unroll
            for (int mf = 0; mf < 4; mf++)
#pragma unroll
                for (int nf = 0; nf < 4; nf++) {
                    const int p = nf >> 1, s = (nf & 1) * 2;
                    float* c = acc[mf][nf];
                    MMA_F16(c[0], c[1], c[2], c[3],
                            ahi[mf][0], ahi[mf][1], ahi[mf][2], ahi[mf][3],
                            bb[p][s], bb[p][s + 1]);
                    MMA_F16(c[0], c[1], c[2], c[3],
                            alo[mf][0], alo[mf][1], alo[mf][2], alo[mf][3],
                            bb[p][s], bb[p][s + 1]);
                }
        }
    }

    __syncthreads();
    float* zs = (float*)smp;
    {
        const int cr = lane >> 2, cc = (lane & 3) * 2;
#pragma unroll
        for (int mf = 0; mf < 4; mf++)
#pragma unroll
            for (int nf = 0; nf < 4; nf++) {
                int row = wm + mf * 16 + cr;
                int col = wn + nf * 8 + cc;
                *(float2*)&zs[row * 128 + col]       = make_float2(acc[mf][nf][0], acc[mf][nf][1]);
                *(float2*)&zs[(row + 8) * 128 + col] = make_float2(acc[mf][nf][2], acc[mf][nf][3]);
            }
    }
    __syncthreads();

    const int cseg = tid & 31;
    float4 bv = __ldg((const float4*)(bias + n0 + cseg * 4));
#pragma unroll
    for (int i = 0; i < 16; i++) {
        int r = i * 8 + (tid >> 5);
        float4 v = *(const float4*)&zs[r * 128 + cseg * 4];
        v.x += bv.x; v.y += bv.y; v.z += bv.z; v.w += bv.w;
        *(float4*)(g_zpre + ((size_t)b * kT + r) * kG + n0 + cseg * 4) = v;
    }
}

// ---------------- persistent LSTM recurrence: U smem-resident ----------------
// grid (16 nt, 8 mt) = 128 CTAs, all resident (1/SM). 256 thr (8 warps 2x4),
// warp tile 32x32. Per CTA: M=64 batch x N=128 n', K=512 in one resident pass.
// SMEM: U 128KB (loaded once) + A(h) 64KB (TMA per step) + z-stage 32KB = 224KB.
// h exchanged via double-buffered global staging + per-mt 16-CTA atomic barrier.
#define RK_A_OFF 131072
#define RK_Z_OFF 196608
#define RK_DYN   229376

extern "C" __global__ void __launch_bounds__(256, 1) lstm_persist_kernel(
    const int* __restrict__ seq,
    const float* __restrict__ h0,
    const float* __restrict__ c0,
    float* __restrict__ out)
{
    extern __shared__ __align__(1024) char smp[];
    __shared__ __align__(8) uint64_t mbar_s;
    const uint32_t smb = smem_u32(smp);
    const uint32_t mb = smem_u32(&mbar_s);

    const int tid = threadIdx.x;
    const int wid = tid >> 5, lane = tid & 31;
    const int nt = blockIdx.x, mt = blockIdx.y;
    const int b0 = mt * 64;
    const int u0g = nt * 32;

    if (tid == 0) {
        MBAR_INIT(mb, 1);
        asm volatile("fence.proxy.async.shared::cta;" ::: "memory");
    }
    __syncthreads();
    if (tid == 0) {
        MBAR_EXPECT_TX(mb, 196608u);
        TMA_BULK(smb,            g_ur + (size_t)nt * 65536, 131072u, mb);   // U resident
        TMA_BULK(smb + RK_A_OFF, g_hx[0] + (size_t)mt * 32768, 65536u, mb); // h0
    }

    // ---- per-thread state ----
    const int ul = tid & 31;
    const int rw = tid >> 5;           // 0..7 (row group)
    float creg[8], zpf[8][4];
    int seqv[8];
#pragma unroll
    for (int it = 0; it < 8; it++) {
        int b = b0 + it * 8 + rw;
        creg[it] = __ldg(c0 + (size_t)b * kUnits + u0g + ul);
    }
    auto prefetch_z = [&](int t) {
#pragma unroll
        for (int it = 0; it < 8; it++) {
            int b = b0 + it * 8 + rw;
            const float* zp = g_zpre + ((size_t)b * kT + t) * kG;
#pragma unroll
            for (int g = 0; g < 4; g++)
                zpf[it][g] = __ldg(zp + g * kUnits + u0g + ul);
            seqv[it] = __ldg(seq + (size_t)b * kT + t);
        }
    };
    prefetch_z(0);

    const int wm = (wid & 1) * 32;
    const int wn = (wid >> 1) * 32;
    const int la7 = lane & 7;
    const int arow_off = (lane >> 3) & 1;
    const int akseg   = (lane >> 4) & 1;
    const int brow_off = (lane >> 4) & 1;
    const int bkseg   = (lane >> 3) & 1;

    float* zs = (float*)(smp + RK_Z_OFF);
    float* hfin = out + (size_t)kB * kT * kUnits;
    float* cfin = hfin + (size_t)kB * kUnits;
    const int qw = nt * 4 + (ul >> 3);   // q of this thread's unit in h-row layout
    const int lnw = ul & 7;

    for (int t = 0; t < kT; t++) {
        MBAR_WAIT(mb, t & 1);            // A(h_{t-1}) resident

        float acc[2][4][4];
#pragma unroll
        for (int i = 0; i < 2; i++)
#pragma unroll
            for (int j = 0; j < 4; j++)
#pragma unroll
                for (int q = 0; q < 4; q++) acc[i][j][q] = 0.f;

        // ---- GEMM: 32 ksteps over resident smem ----
#pragma unroll 4
        for (int ks = 0; ks < 32; ks++) {
            uint32_t aa[2][4], bb[2][4];
            const int qA = ks * 2 + akseg;
            const int qB = ks * 2 + bkseg;
#pragma unroll
            for (int mf = 0; mf < 2; mf++) {
                int row = wm + mf * 16 + la7 + arow_off * 8;
                uint32_t off = (uint32_t)(row * 1024 + (((qA & 56) | ((qA ^ row) & 7)) << 4));
                LDMATRIX_X4(aa[mf][0], aa[mf][1], aa[mf][2], aa[mf][3], smb + RK_A_OFF + off);
            }
#pragma unroll
            for (int p = 0; p < 2; p++) {
                int row = wn + p * 16 + la7 + brow_off * 8;
                uint32_t off = (uint32_t)(row * 1024 + (((qB & 56) | ((qB ^ row) & 7)) << 4));
                LDMATRIX_X4(bb[p][0], bb[p][1], bb[p][2], bb[p][3], smb + off);
            }
#pragma unroll
            for (int mf = 0; mf < 2; mf++)
#pragma unroll
                for (int nf = 0; nf < 4; nf++) {
                    const int p = nf >> 1, s = (nf & 1) * 2;
                    float* c = acc[mf][nf];
                    MMA_F16(c[0], c[1], c[2], c[3],
                            aa[mf][0], aa[mf][1], aa[mf][2], aa[mf][3],
                            bb[p][s], bb[p][s + 1]);
                }
        }

        // ---- stage z ----
        __syncthreads();
        {
            const int cr = lane >> 2, cc = (lane & 3) * 2;
#pragma unroll
            for (int mf = 0; mf < 2; mf++)
#pragma unroll
                for (int nf = 0; nf < 4; nf++) {
                    int row = wm + mf * 16 + cr;
                    int col = wn + nf * 8 + cc;
                    *(float2*)&zs[row * 128 + col]       = make_float2(acc[mf][nf][0], acc[mf][nf][1]);
                    *(float2*)&zs[(row + 8) * 128 + col] = make_float2(acc[mf][nf][2], acc[mf][nf][3]);
                }
        }
        __syncthreads();

        // ---- fused LSTM epilogue ----
        __half* hx = g_hx[(t + 1) & 1] + (size_t)mt * 32768;
        const bool lastt = (t == kT - 1);
        const float* hprev = (t == 0) ? h0 : (out + (size_t)(t - 1) * kUnits);
        const int hstride = (t == 0) ? kUnits : (kT * kUnits);
#pragma unroll
        for (int it = 0; it < 8; it++) {
            int rb = it * 8 + rw;
            int b = b0 + rb;
            int u = u0g + ul;
            float4 z4 = *(const float4*)&zs[rb * 128 + ul * 4];
            float zi = z4.x + zpf[it][0];
            float zf = z4.y + zpf[it][1];
            float zg = z4.z + zpf[it][2];
            float zo = z4.w + zpf[it][3];
            float ig = fast_sig(zi);
            float fg = fast_sig(zf);
            float og = fast_sig(zo);
            float cold = creg[it];
            float cnew = fmaf(fg, cold, ig * fast_tanh(zg));
            float hnew = og * fast_tanh(cnew);
            if (seqv[it] == 0) {
                cnew = cold;
                hnew = __ldg(hprev + (size_t)b * hstride + u);
            }
            creg[it] = cnew;
            out[(size_t)b * (kT * kUnits) + (size_t)t * kUnits + u] = hnew;
            hx[rb * 512 + ((qw & 56) | ((qw ^ rb) & 7)) * 8 + lnw] = __float2half_rn(hnew);
            if (lastt) {
                hfin[(size_t)b * kUnits + u] = hnew;
                cfin[(size_t)b * kUnits + u] = cnew;
            }
        }
        if (t == kT - 1) break;

        prefetch_z(t + 1);

        // ---- 16-CTA barrier (per mt), then fetch exchanged h ----
        __threadfence();
        __syncthreads();
        if (tid == 0) {
            asm volatile("red.release.gpu.global.add.u32 [%0], 1;"
                         :: "l"(&g_bar[mt]) : "memory");
            unsigned target = 16u * (unsigned)(t + 1);
            unsigned v;
            do {
                asm volatile("ld.acquire.gpu.global.u32 %0, [%1];"
                             : "=r"(v) : "l"(&g_bar[mt]) : "memory");
                if (v < target) __nanosleep(32);
            } while (v < target);
        }
        __syncthreads();
        if (tid == 0) {
            MBAR_EXPECT_TX(mb, 65536u);
            TMA_BULK(smb + RK_A_OFF, g_hx[(t + 1) & 1] + (size_t)mt * 32768, 65536u, mb);
        }
    }
}

// ---------------- host ----------------
extern "C" void kernel_launch(void* const* d_in, const int* in_sizes, int n_in,
                              void* d_out, int out_size)
{
    const int*   seq  = (const int*)d_in[0];
    const float* h0   = (const float*)d_in[1];
    const float* c0   = (const float*)d_in[2];
    const float* emb  = (const float*)d_in[3];
    const float* W    = (const float*)d_in[4];
    const float* Umat = (const float*)d_in[5];
    const float* bias = (const float*)d_in[6];
    float* out = (float*)d_out;

    static int configured = 0;
    if (!configured) {
        cudaFuncSetAttribute(precompute_mma_kernel, cudaFuncAttributeMaxDynamicSharedMemorySize, PC_DYN);
        cudaFuncSetAttribute(lstm_persist_kernel, cudaFuncAttributeMaxDynamicSharedMemorySize, RK_DYN);
        configured = 1;
    }

    const int embBlocks = (kVocab + 7) / 8;
    prep_kernel<<<kG + 8 + kG + embBlocks, 128>>>(Umat, h0, W, emb);

    precompute_mma_kernel<<<dim3(16, kB), 256, PC_DYN>>>(seq, bias);

    lstm_persist_kernel<<<dim3(16, 8), 256, RK_DYN>>>(seq, h0, c0, out);
}